// round 2
// baseline (speedup 1.0000x reference)
#include <cuda_runtime.h>

// DenselyCnnAttLayer: out[b,s,d] = sum_l softmax_m( sum_l' s[b,s,l'] * Ws[s,l',m] )[l] * x_l[b,s,d]
// where s[b,s,l] = sum_d x_l[b,s,d].  B=64, S=512, L=6, D=512, fp32.
//
// R2 change vs R1 (70.4us, DRAM 83.5%, occ 45% @ 64 regs):
//  - Stage the 6 per-thread float4 payloads in SMEM (thread-private slots)
//    instead of holding them in registers across the block barrier. This cuts
//    live registers from 64 to ~48, letting 10 CTAs/SM (vs 8) keep more loads
//    in flight -> closer to the ~7.2TB/s streaming ceiling.
//  - __ldcs / __stcs streaming hints (each global element is touched once).
// Traffic is already minimal: 6 reads + 1 write of [B,S,D] = ~470 MB.

#define DD   512
#define LL   6
#define NTHR 128   // DD/4 float4 lanes

__global__ __launch_bounds__(NTHR, 10)
void dense_att_kernel(const float* __restrict__ x0,
                      const float* __restrict__ x1,
                      const float* __restrict__ x2,
                      const float* __restrict__ x3,
                      const float* __restrict__ x4,
                      const float* __restrict__ x5,
                      const float* __restrict__ Ws,   // [S, L, L]
                      float* __restrict__ out,        // [B, S, D]
                      int S)
{
    const int row = blockIdx.x;          // b*S + s
    const int s   = row & (S - 1);       // S is a power of two (512)
    const int tid = threadIdx.x;

    __shared__ float4 sv[LL * NTHR];     // staged payload, 12 KB
    __shared__ float  sW[LL * LL];       // Ws[s] tile
    __shared__ float  ssum[NTHR / 32][LL];

    if (tid < LL * LL) {
        sW[tid] = Ws[(size_t)s * (LL * LL) + tid];
    }

    const size_t base = (size_t)row * DD + (size_t)tid * 4;

    // Pass 1: stream-load the 6 layer fragments, stash in smem, fold into
    // per-layer partial sums. Registers for the payload die here.
    float p[LL];
    {
        const float* xs[LL] = {x0, x1, x2, x3, x4, x5};
#pragma unroll
        for (int j = 0; j < LL; j++) {
            float4 t = __ldcs(reinterpret_cast<const float4*>(xs[j] + base));
            sv[j * NTHR + tid] = t;
            p[j] = (t.x + t.y) + (t.z + t.w);
        }
    }

    // Warp-level reduction of the 6 per-layer partial sums.
#pragma unroll
    for (int off = 16; off > 0; off >>= 1) {
#pragma unroll
        for (int j = 0; j < LL; j++) {
            p[j] += __shfl_xor_sync(0xffffffffu, p[j], off);
        }
    }

    const int warp = tid >> 5;
    const int lane = tid & 31;
    if (lane == 0) {
#pragma unroll
        for (int j = 0; j < LL; j++) ssum[warp][j] = p[j];
    }
    __syncthreads();

    // Every thread finalizes the 6 sums + tiny softmax redundantly
    // (cheaper than a second barrier + broadcast).
    float lsum[LL];
#pragma unroll
    for (int j = 0; j < LL; j++) {
        lsum[j] = (ssum[0][j] + ssum[1][j]) + (ssum[2][j] + ssum[3][j]);
    }

    float logit[LL];
#pragma unroll
    for (int m = 0; m < LL; m++) logit[m] = 0.0f;
#pragma unroll
    for (int l = 0; l < LL; l++) {
        const float sl = lsum[l];
#pragma unroll
        for (int m = 0; m < LL; m++) {
            logit[m] = fmaf(sl, sW[l * LL + m], logit[m]);
        }
    }

    float mx = logit[0];
#pragma unroll
    for (int m = 1; m < LL; m++) mx = fmaxf(mx, logit[m]);
    float a[LL];
    float den = 0.0f;
#pragma unroll
    for (int m = 0; m < LL; m++) {
        a[m] = __expf(logit[m] - mx);
        den += a[m];
    }
    const float inv = __frcp_rn(den);
#pragma unroll
    for (int m = 0; m < LL; m++) a[m] *= inv;

    // Pass 2: read back own slots from smem (no sync needed — same thread
    // wrote them), weighted combine, one coalesced streaming store.
    float4 o;
    o.x = o.y = o.z = o.w = 0.0f;
#pragma unroll
    for (int j = 0; j < LL; j++) {
        float4 t = sv[j * NTHR + tid];
        o.x = fmaf(a[j], t.x, o.x);
        o.y = fmaf(a[j], t.y, o.y);
        o.z = fmaf(a[j], t.z, o.z);
        o.w = fmaf(a[j], t.w, o.w);
    }
    __stcs(reinterpret_cast<float4*>(out + base), o);
}

extern "C" void kernel_launch(void* const* d_in, const int* in_sizes, int n_in,
                              void* d_out, int out_size)
{
    const float* x0 = (const float*)d_in[0];
    const float* x1 = (const float*)d_in[1];
    const float* x2 = (const float*)d_in[2];
    const float* x3 = (const float*)d_in[3];
    const float* x4 = (const float*)d_in[4];
    const float* x5 = (const float*)d_in[5];
    const float* Ws = (const float*)d_in[6];
    float* out = (float*)d_out;

    const int rows = in_sizes[0] / DD;          // B*S
    const int S    = in_sizes[6] / (LL * LL);   // 512

    dense_att_kernel<<<rows, NTHR>>>(x0, x1, x2, x3, x4, x5, Ws, out, S);
}

// round 3
// speedup vs baseline: 1.1164x; 1.1164x over previous
#include <cuda_runtime.h>

// DenselyCnnAttLayer, warp-per-row formulation.
// out[b,s,d] = sum_l softmax_m( sum_l' s[b,s,l'] * Ws[s,l',m] )[l] * x_l[b,s,d]
// B=64, S=512, L=6, D=512, fp32. Minimal traffic: 6 reads + 1 write = ~470MB.
//
// R3 vs R1 (70.4us, DRAM 83.5%): R2's smem staging regressed (L1tex pipe hit
// 80.8%). Instead: one WARP per (b,s) row. Each lane holds 4 float4 per layer
// (24 LDG.128 per warp, front-batched). No __syncthreads, no smem, reduction
// is shuffle-only, softmax redundant per lane. 2x bytes-in-flight per SM.

#define DD    512
#define LL    6
#define CHNK  4            // float4 chunks per lane per layer (512/32/4)
#define NTHR  128          // 4 warps = 4 rows per CTA

__global__ __launch_bounds__(NTHR, 4)
void dense_att_kernel(const float* __restrict__ x0,
                      const float* __restrict__ x1,
                      const float* __restrict__ x2,
                      const float* __restrict__ x3,
                      const float* __restrict__ x4,
                      const float* __restrict__ x5,
                      const float* __restrict__ Ws,   // [S, L, L]
                      float* __restrict__ out)        // [B, S, D]
{
    const int warp = threadIdx.x >> 5;
    const int lane = threadIdx.x & 31;
    const int row  = blockIdx.x * (NTHR / 32) + warp;   // b*S + s
    const int s    = row & 511;                          // S = 512

    // lane handles float4s at d = c*128 + lane*4, c = 0..3 (coalesced)
    const size_t base = (size_t)row * DD + (size_t)lane * 4;

    const float* xs[LL] = {x0, x1, x2, x3, x4, x5};

    float4 v[LL][CHNK];
    float  p[LL];

#pragma unroll
    for (int j = 0; j < LL; j++) {
#pragma unroll
        for (int c = 0; c < CHNK; c++) {
            v[j][c] = __ldcs(reinterpret_cast<const float4*>(xs[j] + base + c * 128));
        }
    }

#pragma unroll
    for (int j = 0; j < LL; j++) {
        float a0 = (v[j][0].x + v[j][0].y) + (v[j][0].z + v[j][0].w);
        float a1 = (v[j][1].x + v[j][1].y) + (v[j][1].z + v[j][1].w);
        float a2 = (v[j][2].x + v[j][2].y) + (v[j][2].z + v[j][2].w);
        float a3 = (v[j][3].x + v[j][3].y) + (v[j][3].z + v[j][3].w);
        p[j] = (a0 + a1) + (a2 + a3);
    }

    // Warp butterfly: all lanes end with the full per-layer sums.
#pragma unroll
    for (int off = 16; off > 0; off >>= 1) {
#pragma unroll
        for (int j = 0; j < LL; j++) {
            p[j] += __shfl_xor_sync(0xffffffffu, p[j], off);
        }
    }

    // Redundant per-lane 6x6 projection + softmax. Ws loads are warp-uniform
    // (broadcast) and L1-hot after the first touch.
    const float* W = Ws + (size_t)s * (LL * LL);
    float logit[LL];
#pragma unroll
    for (int m = 0; m < LL; m++) logit[m] = 0.0f;
#pragma unroll
    for (int l = 0; l < LL; l++) {
        const float sl = p[l];
#pragma unroll
        for (int m = 0; m < LL; m++) {
            logit[m] = fmaf(sl, __ldg(W + l * LL + m), logit[m]);
        }
    }

    float mx = logit[0];
#pragma unroll
    for (int m = 1; m < LL; m++) mx = fmaxf(mx, logit[m]);
    float a[LL];
    float den = 0.0f;
#pragma unroll
    for (int m = 0; m < LL; m++) {
        a[m] = __expf(logit[m] - mx);
        den += a[m];
    }
    const float inv = __frcp_rn(den);
#pragma unroll
    for (int m = 0; m < LL; m++) a[m] *= inv;

    // Weighted combine over layers, 4 coalesced streaming stores.
#pragma unroll
    for (int c = 0; c < CHNK; c++) {
        float4 o;
        o.x = o.y = o.z = o.w = 0.0f;
#pragma unroll
        for (int j = 0; j < LL; j++) {
            o.x = fmaf(a[j], v[j][c].x, o.x);
            o.y = fmaf(a[j], v[j][c].y, o.y);
            o.z = fmaf(a[j], v[j][c].z, o.z);
            o.w = fmaf(a[j], v[j][c].w, o.w);
        }
        __stcs(reinterpret_cast<float4*>(out + base + c * 128), o);
    }
}

extern "C" void kernel_launch(void* const* d_in, const int* in_sizes, int n_in,
                              void* d_out, int out_size)
{
    const float* x0 = (const float*)d_in[0];
    const float* x1 = (const float*)d_in[1];
    const float* x2 = (const float*)d_in[2];
    const float* x3 = (const float*)d_in[3];
    const float* x4 = (const float*)d_in[4];
    const float* x5 = (const float*)d_in[5];
    const float* Ws = (const float*)d_in[6];
    float* out = (float*)d_out;

    const int rows = in_sizes[0] / DD;          // B*S = 32768
    dense_att_kernel<<<rows / (NTHR / 32), NTHR>>>(x0, x1, x2, x3, x4, x5, Ws, out);
}